// round 8
// baseline (speedup 1.0000x reference)
#include <cuda_runtime.h>
#include <cstdint>

#define HID   8
#define OBS   8
#define CTRL  2
#define WIDTH 256
#define BB    8192
#define TT    256

// ---------------- scratch (no allocations allowed) ----------------
__device__ float g_h[BB * HID];            // final hidden states [B,8]
__device__ float g_w1t[WIDTH * WIDTH];     // W1 transposed: w1t[k*256 + o] = W1[o][k]

// ---------------- f32x2 helpers (sm_100+ packed fp32 FMA) ----------------
typedef unsigned long long u64;

__device__ __forceinline__ u64 pack2(float lo, float hi) {
    u64 r;
    asm("mov.b64 %0, {%1, %2};" : "=l"(r) : "r"(__float_as_uint(lo)), "r"(__float_as_uint(hi)));
    return r;
}
__device__ __forceinline__ void unpack2(u64 v, float& lo, float& hi) {
    unsigned a, b;
    asm("mov.b64 {%0, %1}, %2;" : "=r"(a), "=r"(b) : "l"(v));
    lo = __uint_as_float(a);
    hi = __uint_as_float(b);
}
__device__ __forceinline__ u64 ffma2(u64 a, u64 b, u64 c) {
    u64 d;
    asm("fma.rn.f32x2 %0, %1, %2, %3;" : "=l"(d) : "l"(a), "l"(b), "l"(c));
    return d;
}

// ---------------- kernel 1: Wilson-Cowan recurrence (+ fused W1 transpose) ----------------
// 8 lanes per batch element. Lane i owns h[i], W_A row i, W_B row i.
// x is LOADED directly by every lane (broadcast-coalesced within the 8-lane
// group); only the h exchange uses shuffles (8/step). Last iteration peeled
// so the steady-state loop has no prefetch clamp (pure pointer increments).
//
// Prologue also performs the one-time W1 transpose: this kernel has exactly
// 65536 threads (matching W1's 256*256 elements) and never reads g_w1t, so
// each thread emits one transpose element. g_w1t is only read by k_dec,
// which launches after this kernel retires -> ordering is guaranteed by the
// stream. This removes a separate launch and hides the strided W1 reads
// under the recurrence's streaming phase.
__global__ void __launch_bounds__(256) k_recur(
    const float* __restrict__ state_seq,    // [B,T,8]
    const float* __restrict__ control_seq,  // [B,T,2]
    const float* __restrict__ W_A,          // [8,8]
    const float* __restrict__ W_B,          // [8,10]
    const float* __restrict__ W1)           // [256,256]
{
    int gt = blockIdx.x * 256 + threadIdx.x;   // B*8 = 65536 threads

    // fused one-time transpose: g_w1t[k*256+o] = W1[o*256+k]
    {
        int o = gt & (WIDTH - 1);
        int k = gt >> 8;
        g_w1t[gt] = W1[o * WIDTH + k];
    }

    int b = gt >> 3;
    int i = gt & 7;

    float wa[HID];
    float wb[OBS + CTRL];
#pragma unroll
    for (int j = 0; j < HID; j++) wa[j] = W_A[i * HID + j];
#pragma unroll
    for (int j = 0; j < OBS + CTRL; j++) wb[j] = W_B[i * (OBS + CTRL) + j];

    const float4* sp = (const float4*)(state_seq + (size_t)b * TT * OBS);  // 2 float4 / step
    const float2* cp = (const float2*)(control_seq + (size_t)b * TT * CTRL);

    float h = 0.0f;
    float4 xa = sp[0];
    float4 xb = sp[1];
    float2 c  = cp[0];
    sp += 2;
    cp += 1;

#pragma unroll 2
    for (int t = 0; t < TT - 1; t++) {
        // prefetch next step's inputs (hide DRAM/L2 latency behind compute)
        float4 xa_n = sp[0];
        float4 xb_n = sp[1];
        float2 c_n  = cp[0];
        sp += 2;
        cp += 1;

        float acc = wb[OBS] * c.x + wb[OBS + 1] * c.y;
        acc += wb[0] * xa.x + wb[1] * xa.y + wb[2] * xa.z + wb[3] * xa.w;
        acc += wb[4] * xb.x + wb[5] * xb.y + wb[6] * xb.z + wb[7] * xb.w;
#pragma unroll
        for (int j = 0; j < HID; j++)
            acc += wa[j] * __shfl_sync(0xffffffffu, h, j, 8);

        h = __fdividef(1.0f, 1.0f + __expf(-acc));   // sigmoid

        xa = xa_n; xb = xb_n; c = c_n;
    }

    // peeled final step (t = TT-1), inputs already in registers
    {
        float acc = wb[OBS] * c.x + wb[OBS + 1] * c.y;
        acc += wb[0] * xa.x + wb[1] * xa.y + wb[2] * xa.z + wb[3] * xa.w;
        acc += wb[4] * xb.x + wb[5] * xb.y + wb[6] * xb.z + wb[7] * xb.w;
#pragma unroll
        for (int j = 0; j < HID; j++)
            acc += wa[j] * __shfl_sync(0xffffffffu, h, j, 8);
        h = __fdividef(1.0f, 1.0f + __expf(-acc));
    }

    g_h[b * HID + i] = h;
}

// ---------------- kernel 2: decoder MLP (10->256->256->1), layer2 fused ----------------
// Block = 256 threads, 32 batch elements per block.
// Thread (og,eg): og = tid&63 -> outputs o = 4*og..4*og+3 ; eg = tid>>6 -> elements 8*eg..8*eg+7
// Layer1 accumulates in packed f32x2 over element pairs (FFMA2: 2 MACs/inst).
// Row stride 36 floats keeps every (k, e0) activation slice 16B-aligned so the
// inner loop uses two LDS.128 instead of four LDS.64.
#define A0_STRIDE 36

__global__ void __launch_bounds__(256) k_dec(
    const float* __restrict__ control,  // [B,2]
    const float* __restrict__ W0,       // [256,10]
    const float* __restrict__ b0,       // [256]
    const float* __restrict__ b1,       // [256]
    const float* __restrict__ W2,       // [1,256]
    const float* __restrict__ b2,       // [1]
    float* __restrict__ out)            // [B]
{
    __shared__ float s_x[32 * 12];               // [e][j], 10 used, pad 12
    __shared__ float s_a0[WIDTH * A0_STRIDE];    // layer0 acts [k][e], 16B-aligned slices
    __shared__ float s_red[8][8];                // per-warp partial q sums

    int tid = threadIdx.x;
    int be0 = blockIdx.x * 32;

    // stage concat(h, control) for 32 elements
    for (int idx = tid; idx < 32 * 10; idx += 256) {
        int e = idx / 10, j = idx % 10;
        float v = (j < 8) ? g_h[(be0 + e) * HID + j]
                          : control[(be0 + e) * CTRL + (j - 8)];
        s_x[e * 12 + j] = v;
    }
    __syncthreads();

    // ---- layer 0: neuron n = tid, all 32 elements ----
    {
        float w[10];
#pragma unroll
        for (int j = 0; j < 10; j++) w[j] = W0[tid * 10 + j];
        float bias = b0[tid];
#pragma unroll 4
        for (int e = 0; e < 32; e++) {
            float a = bias;
#pragma unroll
            for (int j = 0; j < 10; j++) a += w[j] * s_x[e * 12 + j];
            s_a0[tid * A0_STRIDE + e] = fmaxf(a, 0.0f);
        }
    }
    __syncthreads();

    // ---- layer 1 (f32x2) + fused layer 2 ----
    int og = tid & 63;
    int eg = tid >> 6;
    int e0 = eg * 8;   // element pairs: (e0,e0+1) .. (e0+6,e0+7)

    u64 acc[16];       // [i out][p pair], pack2(0,0) == 0
#pragma unroll
    for (int r = 0; r < 16; r++) acc[r] = 0ull;

    const float4* wbase = (const float4*)g_w1t;   // row k: 64 float4s over outputs

#pragma unroll 2
    for (int k = 0; k < WIDTH; k++) {
        float4 w = __ldg(&wbase[k * 64 + og]);    // coalesced LDG.128: 4 consecutive outputs
        u64 wp0 = pack2(w.x, w.x);
        u64 wp1 = pack2(w.y, w.y);
        u64 wp2 = pack2(w.z, w.z);
        u64 wp3 = pack2(w.w, w.w);
        // two LDS.128 (broadcast: all lanes in a warp read the same address)
        const ulonglong2* arow = (const ulonglong2*)(s_a0 + k * A0_STRIDE + e0);
        ulonglong2 aa0 = arow[0];                  // pairs p=0,1
        ulonglong2 aa1 = arow[1];                  // pairs p=2,3
        u64 ap[4] = { aa0.x, aa0.y, aa1.x, aa1.y };
#pragma unroll
        for (int p = 0; p < 4; p++) {
            acc[0 * 4 + p] = ffma2(wp0, ap[p], acc[0 * 4 + p]);
            acc[1 * 4 + p] = ffma2(wp1, ap[p], acc[1 * 4 + p]);
            acc[2 * 4 + p] = ffma2(wp2, ap[p], acc[2 * 4 + p]);
            acc[3 * 4 + p] = ffma2(wp3, ap[p], acc[3 * 4 + p]);
        }
    }

    // epilogue: bias + relu + W2 scale -> per-element partials
    float q[8];
#pragma unroll
    for (int r = 0; r < 8; r++) q[r] = 0.0f;

#pragma unroll
    for (int i = 0; i < 4; i++) {
        int o = og * 4 + i;
        float bv = b1[o];
        float wv = W2[o];
#pragma unroll
        for (int p = 0; p < 4; p++) {
            float lo, hi;
            unpack2(acc[i * 4 + p], lo, hi);
            q[2 * p]     += fmaxf(lo + bv, 0.0f) * wv;
            q[2 * p + 1] += fmaxf(hi + bv, 0.0f) * wv;
        }
    }

    // warp butterfly reduce (all lanes in a warp share the same eg -> same 8 elements)
#pragma unroll
    for (int off = 16; off; off >>= 1) {
#pragma unroll
        for (int r = 0; r < 8; r++)
            q[r] += __shfl_xor_sync(0xffffffffu, q[r], off);
    }
    int warp = tid >> 5;
    if ((tid & 31) == 0) {
#pragma unroll
        for (int r = 0; r < 8; r++) s_red[warp][r] = q[r];
    }
    __syncthreads();

    // combine the two warps per eg group + bias, write output
    if (tid < 32) {
        int e = tid;
        int w0i = (e >> 3) * 2;                       // warps 2m,2m+1 -> eg m
        float val = s_red[w0i][e & 7] + s_red[w0i + 1][e & 7] + b2[0];
        out[be0 + e] = val;
    }
}

// ---------------- launch ----------------
extern "C" void kernel_launch(void* const* d_in, const int* in_sizes, int n_in,
                              void* d_out, int out_size)
{
    const float* state_seq   = (const float*)d_in[0];
    const float* control_seq = (const float*)d_in[1];
    const float* control     = (const float*)d_in[2];
    const float* W_A         = (const float*)d_in[3];
    const float* W_B         = (const float*)d_in[4];
    const float* W0          = (const float*)d_in[5];
    const float* b0          = (const float*)d_in[6];
    const float* W1          = (const float*)d_in[7];
    const float* b1          = (const float*)d_in[8];
    const float* W2          = (const float*)d_in[9];
    const float* b2          = (const float*)d_in[10];
    float* out = (float*)d_out;

    k_recur<<<BB * HID / 256, 256>>>(state_seq, control_seq, W_A, W_B, W1);
    k_dec<<<BB / 32, 256>>>(control, W0, b0, b1, W2, b2, out);
}

// round 13
// speedup vs baseline: 1.7192x; 1.7192x over previous
#include <cuda_runtime.h>
#include <cstdint>

#define HID   8
#define OBS   8
#define CTRL  2
#define WIDTH 256
#define BB    8192
#define TT    256

// ---------------- scratch (no allocations allowed) ----------------
__device__ float g_h[BB * HID];            // final hidden states [B,8]
__device__ float g_w1t[WIDTH * WIDTH];     // W1 transposed: w1t[k*256 + o] = W1[o][k]

// ---------------- f32x2 helpers (sm_100+ packed fp32 FMA) ----------------
typedef unsigned long long u64;

__device__ __forceinline__ u64 pack2(float lo, float hi) {
    u64 r;
    asm("mov.b64 %0, {%1, %2};" : "=l"(r) : "r"(__float_as_uint(lo)), "r"(__float_as_uint(hi)));
    return r;
}
__device__ __forceinline__ void unpack2(u64 v, float& lo, float& hi) {
    unsigned a, b;
    asm("mov.b64 {%0, %1}, %2;" : "=r"(a), "=r"(b) : "l"(v));
    lo = __uint_as_float(a);
    hi = __uint_as_float(b);
}
__device__ __forceinline__ u64 ffma2(u64 a, u64 b, u64 c) {
    u64 d;
    asm("fma.rn.f32x2 %0, %1, %2, %3;" : "=l"(d) : "l"(a), "l"(b), "l"(c));
    return d;
}

// ---------------- kernel 1: Wilson-Cowan recurrence (+ fused W1 transpose) ----------------
// 4 lanes per batch element; lane s owns output rows {2s, 2s+1}.
// Per warp-step: 8 SHFL + 3 LDG serve EIGHT elements (halves MIO pressure per
// element vs the 8-lane layout; round-8 profile fit shows SHFL SMSP throughput
// was the binding constraint). x loads broadcast within each 4-lane group.
// Last iteration peeled so the steady loop is pure pointer increments.
// Prologue performs the one-time W1 transpose (32768 threads x 2 elements).
__global__ void __launch_bounds__(128, 1) k_recur(
    const float* __restrict__ state_seq,    // [B,T,8]
    const float* __restrict__ control_seq,  // [B,T,2]
    const float* __restrict__ W_A,          // [8,8]
    const float* __restrict__ W_B,          // [8,10]
    const float* __restrict__ W1)           // [256,256]
{
    int gt = blockIdx.x * 128 + threadIdx.x;   // B*4 = 32768 threads

    // fused one-time transpose: g_w1t[idx] = W1[(idx&255)*256 + (idx>>8)]
    {
        int idx = gt * 2;
        g_w1t[idx]     = W1[(idx & 255) * WIDTH + (idx >> 8)];
        int idx1 = idx + 1;
        g_w1t[idx1]    = W1[(idx1 & 255) * WIDTH + (idx1 >> 8)];
    }

    int b = gt >> 2;   // batch element
    int s = gt & 3;    // sub-lane: owns rows 2s, 2s+1

    float wa0[HID], wa1[HID], wb0[OBS + CTRL], wb1[OBS + CTRL];
#pragma unroll
    for (int j = 0; j < HID; j++) {
        wa0[j] = W_A[(2 * s) * HID + j];
        wa1[j] = W_A[(2 * s + 1) * HID + j];
    }
#pragma unroll
    for (int j = 0; j < OBS + CTRL; j++) {
        wb0[j] = W_B[(2 * s) * (OBS + CTRL) + j];
        wb1[j] = W_B[(2 * s + 1) * (OBS + CTRL) + j];
    }

    const float4* sp = (const float4*)(state_seq + (size_t)b * TT * OBS);
    const float2* cp = (const float2*)(control_seq + (size_t)b * TT * CTRL);

    float ha = 0.0f, hb = 0.0f;   // h[2s], h[2s+1]
    float4 xa = sp[0];
    float4 xb = sp[1];
    float2 c  = cp[0];
    sp += 2;
    cp += 1;

#pragma unroll 2
    for (int t = 0; t < TT - 1; t++) {
        float4 xa_n = sp[0];
        float4 xb_n = sp[1];
        float2 c_n  = cp[0];
        sp += 2;
        cp += 1;

        // h exchange within 4-lane group: h[2g] from lane g's ha, h[2g+1] from hb
        float h0 = __shfl_sync(0xffffffffu, ha, 0, 4);
        float h1 = __shfl_sync(0xffffffffu, hb, 0, 4);
        float h2 = __shfl_sync(0xffffffffu, ha, 1, 4);
        float h3 = __shfl_sync(0xffffffffu, hb, 1, 4);
        float h4 = __shfl_sync(0xffffffffu, ha, 2, 4);
        float h5 = __shfl_sync(0xffffffffu, hb, 2, 4);
        float h6 = __shfl_sync(0xffffffffu, ha, 3, 4);
        float h7 = __shfl_sync(0xffffffffu, hb, 3, 4);

        // row 2s (same term order as the passing version: control, state, hidden)
        float a0 = wb0[OBS] * c.x + wb0[OBS + 1] * c.y;
        a0 += wb0[0] * xa.x + wb0[1] * xa.y + wb0[2] * xa.z + wb0[3] * xa.w;
        a0 += wb0[4] * xb.x + wb0[5] * xb.y + wb0[6] * xb.z + wb0[7] * xb.w;
        a0 += wa0[0] * h0 + wa0[1] * h1 + wa0[2] * h2 + wa0[3] * h3;
        a0 += wa0[4] * h4 + wa0[5] * h5 + wa0[6] * h6 + wa0[7] * h7;

        // row 2s+1
        float a1 = wb1[OBS] * c.x + wb1[OBS + 1] * c.y;
        a1 += wb1[0] * xa.x + wb1[1] * xa.y + wb1[2] * xa.z + wb1[3] * xa.w;
        a1 += wb1[4] * xb.x + wb1[5] * xb.y + wb1[6] * xb.z + wb1[7] * xb.w;
        a1 += wa1[0] * h0 + wa1[1] * h1 + wa1[2] * h2 + wa1[3] * h3;
        a1 += wa1[4] * h4 + wa1[5] * h5 + wa1[6] * h6 + wa1[7] * h7;

        ha = __fdividef(1.0f, 1.0f + __expf(-a0));
        hb = __fdividef(1.0f, 1.0f + __expf(-a1));

        xa = xa_n; xb = xb_n; c = c_n;
    }

    // peeled final step
    {
        float h0 = __shfl_sync(0xffffffffu, ha, 0, 4);
        float h1 = __shfl_sync(0xffffffffu, hb, 0, 4);
        float h2 = __shfl_sync(0xffffffffu, ha, 1, 4);
        float h3 = __shfl_sync(0xffffffffu, hb, 1, 4);
        float h4 = __shfl_sync(0xffffffffu, ha, 2, 4);
        float h5 = __shfl_sync(0xffffffffu, hb, 2, 4);
        float h6 = __shfl_sync(0xffffffffu, ha, 3, 4);
        float h7 = __shfl_sync(0xffffffffu, hb, 3, 4);

        float a0 = wb0[OBS] * c.x + wb0[OBS + 1] * c.y;
        a0 += wb0[0] * xa.x + wb0[1] * xa.y + wb0[2] * xa.z + wb0[3] * xa.w;
        a0 += wb0[4] * xb.x + wb0[5] * xb.y + wb0[6] * xb.z + wb0[7] * xb.w;
        a0 += wa0[0] * h0 + wa0[1] * h1 + wa0[2] * h2 + wa0[3] * h3;
        a0 += wa0[4] * h4 + wa0[5] * h5 + wa0[6] * h6 + wa0[7] * h7;

        float a1 = wb1[OBS] * c.x + wb1[OBS + 1] * c.y;
        a1 += wb1[0] * xa.x + wb1[1] * xa.y + wb1[2] * xa.z + wb1[3] * xa.w;
        a1 += wb1[4] * xb.x + wb1[5] * xb.y + wb1[6] * xb.z + wb1[7] * xb.w;
        a1 += wa1[0] * h0 + wa1[1] * h1 + wa1[2] * h2 + wa1[3] * h3;
        a1 += wa1[4] * h4 + wa1[5] * h5 + wa1[6] * h6 + wa1[7] * h7;

        ha = __fdividef(1.0f, 1.0f + __expf(-a0));
        hb = __fdividef(1.0f, 1.0f + __expf(-a1));
    }

    g_h[b * HID + 2 * s]     = ha;
    g_h[b * HID + 2 * s + 1] = hb;
}

// ---------------- kernel 2: decoder MLP (10->256->256->1), layer2 fused ----------------
// 512 threads/block, 32 batch elements/block, 256 blocks.
// Thread (og,eg): og = tid&63 -> outputs 4og..4og+3 ; eg = tid>>6 (0..7) -> elems 4eg..4eg+3.
// 8 u64 accumulators/thread (16 regs -> no spills under the reg cap of
// __launch_bounds__(512,2); round-8 profile showed regs=48 + issue=12% = spill).
#define A0_STRIDE 36

__global__ void __launch_bounds__(512, 2) k_dec(
    const float* __restrict__ control,  // [B,2]
    const float* __restrict__ W0,       // [256,10]
    const float* __restrict__ b0,       // [256]
    const float* __restrict__ b1,       // [256]
    const float* __restrict__ W2,       // [1,256]
    const float* __restrict__ b2,       // [1]
    float* __restrict__ out)            // [B]
{
    __shared__ float s_x[32 * 12];               // [e][j], 10 used, pad 12
    __shared__ float s_a0[WIDTH * A0_STRIDE];    // layer0 acts [k][e], 16B-aligned slices
    __shared__ float s_red[16][4];               // per-warp partial q sums

    int tid = threadIdx.x;
    int be0 = blockIdx.x * 32;

    // stage concat(h, control) for 32 elements (320 values)
    if (tid < 320) {
        int e = tid / 10, j = tid % 10;
        float v = (j < 8) ? g_h[(be0 + e) * HID + j]
                          : control[(be0 + e) * CTRL + (j - 8)];
        s_x[e * 12 + j] = v;
    }
    __syncthreads();

    // ---- layer 0: neuron n = tid&255, half = tid>>8 -> 16 elements each ----
    {
        int n = tid & 255;
        int ebase = (tid >> 8) * 16;
        float w[10];
#pragma unroll
        for (int j = 0; j < 10; j++) w[j] = W0[n * 10 + j];
        float bias = b0[n];
#pragma unroll 4
        for (int e2 = 0; e2 < 16; e2++) {
            int e = ebase + e2;
            float a = bias;
#pragma unroll
            for (int j = 0; j < 10; j++) a += w[j] * s_x[e * 12 + j];
            s_a0[n * A0_STRIDE + e] = fmaxf(a, 0.0f);
        }
    }
    __syncthreads();

    // ---- layer 1 (f32x2) + fused layer 2 ----
    int og = tid & 63;
    int eg = tid >> 6;      // 0..7
    int e0 = eg * 4;        // 4 elements = 2 f32x2 pairs

    u64 acc[8];             // [i out 0..3][p pair 0..1]
#pragma unroll
    for (int r = 0; r < 8; r++) acc[r] = 0ull;

    const float4* wbase = (const float4*)g_w1t;   // row k: 64 float4s over outputs

#pragma unroll 4
    for (int k = 0; k < WIDTH; k++) {
        float4 w = __ldg(&wbase[k * 64 + og]);    // coalesced LDG.128
        u64 wp0 = pack2(w.x, w.x);
        u64 wp1 = pack2(w.y, w.y);
        u64 wp2 = pack2(w.z, w.z);
        u64 wp3 = pack2(w.w, w.w);
        // one LDS.128 broadcast (same address across the warp), 16B-aligned:
        // byte offset = (k*36 + 4*eg)*4 = 144k + 16eg
        const ulonglong2* arow = (const ulonglong2*)(s_a0 + k * A0_STRIDE + e0);
        ulonglong2 aa = arow[0];                  // aa.x = elems e0,e0+1; aa.y = e0+2,e0+3
        acc[0] = ffma2(wp0, aa.x, acc[0]);
        acc[1] = ffma2(wp0, aa.y, acc[1]);
        acc[2] = ffma2(wp1, aa.x, acc[2]);
        acc[3] = ffma2(wp1, aa.y, acc[3]);
        acc[4] = ffma2(wp2, aa.x, acc[4]);
        acc[5] = ffma2(wp2, aa.y, acc[5]);
        acc[6] = ffma2(wp3, aa.x, acc[6]);
        acc[7] = ffma2(wp3, aa.y, acc[7]);
    }

    // epilogue: bias + relu + W2 scale -> per-element partials q[0..3]
    float q[4] = {0.0f, 0.0f, 0.0f, 0.0f};
#pragma unroll
    for (int i = 0; i < 4; i++) {
        int o = og * 4 + i;
        float bv = b1[o];
        float wv = W2[o];
        float lo, hi;
        unpack2(acc[i * 2 + 0], lo, hi);
        q[0] += fmaxf(lo + bv, 0.0f) * wv;
        q[1] += fmaxf(hi + bv, 0.0f) * wv;
        unpack2(acc[i * 2 + 1], lo, hi);
        q[2] += fmaxf(lo + bv, 0.0f) * wv;
        q[3] += fmaxf(hi + bv, 0.0f) * wv;
    }

    // warp butterfly reduce (each warp has a single eg; og spans 32 values)
#pragma unroll
    for (int off = 16; off; off >>= 1) {
#pragma unroll
        for (int r = 0; r < 4; r++)
            q[r] += __shfl_xor_sync(0xffffffffu, q[r], off);
    }
    int warp = tid >> 5;    // 0..15; warps 2m,2m+1 share eg=m (og halves)
    if ((tid & 31) == 0) {
#pragma unroll
        for (int r = 0; r < 4; r++) s_red[warp][r] = q[r];
    }
    __syncthreads();

    // combine the two warps per eg + bias, write output
    if (tid < 32) {
        int e = tid;
        int m = e >> 2;                     // eg
        int r = e & 3;
        float val = s_red[2 * m][r] + s_red[2 * m + 1][r] + b2[0];
        out[be0 + e] = val;
    }
}

// ---------------- launch ----------------
extern "C" void kernel_launch(void* const* d_in, const int* in_sizes, int n_in,
                              void* d_out, int out_size)
{
    const float* state_seq   = (const float*)d_in[0];
    const float* control_seq = (const float*)d_in[1];
    const float* control     = (const float*)d_in[2];
    const float* W_A         = (const float*)d_in[3];
    const float* W_B         = (const float*)d_in[4];
    const float* W0          = (const float*)d_in[5];
    const float* b0          = (const float*)d_in[6];
    const float* W1          = (const float*)d_in[7];
    const float* b1          = (const float*)d_in[8];
    const float* W2          = (const float*)d_in[9];
    const float* b2          = (const float*)d_in[10];
    float* out = (float*)d_out;

    k_recur<<<BB * 4 / 128, 128>>>(state_seq, control_seq, W_A, W_B, W1);
    k_dec<<<BB / 32, 512>>>(control, W0, b0, b1, W2, b2, out);
}